// round 13
// baseline (speedup 1.0000x reference)
#include <cuda_runtime.h>
#include <cuda_fp16.h>
#include <math.h>

#define SEQ   4096
#define CDIM  768
#define NHEAD 12
#define HD    64

// ---------------- scratch ---------------------------------------------------
__device__ __align__(16) __half g_hs[SEQ * CDIM];
__device__ __align__(16) __half g_wq[CDIM * CDIM];
__device__ __align__(16) __half g_wk[CDIM * CDIM];
__device__ __align__(16) __half g_wv[CDIM * CDIM];
__device__ __align__(16) __half g_wo[CDIM * CDIM];
__device__ __align__(16) __half g_q[NHEAD * SEQ * HD];   // fp16, pre-scaled 0.125*log2e
__device__ __align__(16) __half g_k[NHEAD * SEQ * HD];   // fp16 [head][s][d]
__device__ __align__(16) __half g_v[NHEAD * SEQ * HD];   // fp16 [head][s/64][d][s%64]
__device__ __align__(16) float  g_relh[NHEAD * SEQ * 64];  // log2-domain
__device__ __align__(16) float  g_relw[NHEAD * SEQ * 64];  // log2-domain
__device__ __align__(16) __half g_att[SEQ * CDIM];       // attention out (fp16)

#define QSCALE 0.18033688011112042f   /* 0.125 * log2(e) */

// ---------------- helpers ---------------------------------------------------
__device__ __forceinline__ unsigned h2u(float a, float b) {
    __half2 h = __floats2half2_rn(a, b);
    return *(unsigned*)&h;
}
__device__ __forceinline__ unsigned hadd2(unsigned a, unsigned b) {
    unsigned d; asm("add.f16x2 %0, %1, %2;" : "=r"(d) : "r"(a), "r"(b)); return d;
}
__device__ __forceinline__ unsigned ex2h2(unsigned x) {
    unsigned y; asm("ex2.approx.f16x2 %0, %1;" : "=r"(y) : "r"(x)); return y;
}
__device__ __forceinline__ void mma_f16(float4& d,
    unsigned a0, unsigned a1, unsigned a2, unsigned a3,
    unsigned b0, unsigned b1)
{
    asm volatile(
        "mma.sync.aligned.m16n8k16.row.col.f32.f16.f16.f32 "
        "{%0,%1,%2,%3},{%4,%5,%6,%7},{%8,%9},{%0,%1,%2,%3};"
        : "+f"(d.x), "+f"(d.y), "+f"(d.z), "+f"(d.w)
        : "r"(a0), "r"(a1), "r"(a2), "r"(a3), "r"(b0), "r"(b1));
}
__device__ __forceinline__ unsigned ldu(const __half* p) { return *(const unsigned*)p; }

#define LDSM4(d0,d1,d2,d3,addr) \
    asm volatile("ldmatrix.sync.aligned.m8n8.x4.shared.b16 {%0,%1,%2,%3}, [%4];" \
        : "=r"(d0), "=r"(d1), "=r"(d2), "=r"(d3) : "r"(addr))

#define CP16(dst_u32, src_ptr) \
    asm volatile("cp.async.cg.shared.global [%0], [%1], 16;" :: "r"(dst_u32), "l"(src_ptr))
#define CP_COMMIT()  asm volatile("cp.async.commit_group;")
#define CP_WAIT0()   asm volatile("cp.async.wait_group 0;")
#define CP_WAIT1()   asm volatile("cp.async.wait_group 1;")

// ---------------------------------------------------------------------------
// fp32 -> fp16 conversion of hs + 4 weight matrices (one launch).
// ---------------------------------------------------------------------------
#define NG_HS (SEQ * CDIM / 8)
#define NG_W  (CDIM * CDIM / 8)

__global__ __launch_bounds__(256)
void cvt5_kernel(const float* __restrict__ hs,
                 const float* __restrict__ wq, const float* __restrict__ wk,
                 const float* __restrict__ wv, const float* __restrict__ wo)
{
    int i = blockIdx.x * 256 + threadIdx.x;
    const float* src; __half* dst; int j;
    if (i < NG_HS) { src = hs; dst = g_hs; j = i; }
    else {
        i -= NG_HS;
        int w = i / NG_W; j = i - w * NG_W;
        src = (w == 0) ? wq : (w == 1) ? wk : (w == 2) ? wv : wo;
        dst = (w == 0) ? g_wq : (w == 1) ? g_wk : (w == 2) ? g_wv : g_wo;
    }
    float4 a = ((const float4*)src)[2 * j];
    float4 b = ((const float4*)src)[2 * j + 1];
    uint4 o;
    o.x = h2u(a.x, a.y); o.y = h2u(a.z, a.w);
    o.z = h2u(b.x, b.y); o.w = h2u(b.z, b.w);
    ((uint4*)dst)[j] = o;
}

// ===========================================================================
// fp16 GEMM mainloop: cp.async double buffer + ldmatrix fragments (R10 proven).
// ===========================================================================
#define GSH_A (128 * 40)
#define GSH_B (64 * 40)
#define GEMM_SMEM ((2 * GSH_A + 2 * GSH_B) * 2)   // 30720 B

#define GEMM_ISSUE(A_PTR, W_PTR, kc, stage)                                    \
    do {                                                                       \
        _Pragma("unroll")                                                      \
        for (int i_ = 0; i_ < 2; i_++) {                                       \
            int seg = t + i_ * 256, row = seg >> 2, s8 = (seg & 3) * 8;        \
            CP16(sbase + ((stage) * GSH_A + row * 40 + s8) * 2,                \
                 A_PTR + (size_t)(mtile + row) * CDIM + (kc) + s8);            \
        }                                                                      \
        { int row = t >> 2, s8 = (t & 3) * 8;                                  \
          CP16(sbase + (2 * GSH_A + (stage) * GSH_B + row * 40 + s8) * 2,      \
               W_PTR + (size_t)(ntile + row) * CDIM + (kc) + s8); }            \
        CP_COMMIT();                                                           \
    } while (0)

#define GEMM_MAINLOOP_H(A_PTR, W_PTR)                                          \
    float4 acc[2][4];                                                          \
    _Pragma("unroll")                                                          \
    for (int i = 0; i < 2; i++)                                                \
        _Pragma("unroll")                                                      \
        for (int j = 0; j < 4; j++) acc[i][j] = make_float4(0.f,0.f,0.f,0.f);  \
    const unsigned a_lmb =                                                     \
        ((wm + (lane & 15)) * 40 + ((lane >> 4) & 1) * 8) * 2;                 \
    const unsigned b_lmb =                                                     \
        ((wn + (lane & 7) + ((lane >> 4) & 1) * 8) * 40 +                      \
         ((lane >> 3) & 1) * 8) * 2;                                           \
    GEMM_ISSUE(A_PTR, W_PTR, 0, 0);                                            \
    for (int kci = 0; kci < 24; kci++) {                                       \
        const int cur = kci & 1;                                               \
        CP_WAIT0();                                                            \
        __syncthreads();                                                       \
        if (kci < 23) GEMM_ISSUE(A_PTR, W_PTR, (kci + 1) * 32, cur ^ 1);       \
        const unsigned aaddr = sbase + cur * (GSH_A * 2) + a_lmb;              \
        const unsigned baddr = sbase + (2 * GSH_A + cur * GSH_B) * 2 + b_lmb;  \
        _Pragma("unroll")                                                      \
        for (int ks = 0; ks < 2; ks++) {                                       \
            unsigned a[2][4], b[4][2];                                         \
            LDSM4(a[0][0], a[0][1], a[0][2], a[0][3], aaddr + ks * 32);        \
            LDSM4(a[1][0], a[1][1], a[1][2], a[1][3], aaddr + 1280 + ks * 32); \
            LDSM4(b[0][0], b[0][1], b[1][0], b[1][1], baddr + ks * 32);        \
            LDSM4(b[2][0], b[2][1], b[3][0], b[3][1], baddr + 1280 + ks * 32); \
            _Pragma("unroll")                                                  \
            for (int mf = 0; mf < 2; mf++)                                     \
                _Pragma("unroll")                                              \
                for (int nf = 0; nf < 4; nf++)                                 \
                    mma_f16(acc[mf][nf], a[mf][0],a[mf][1],a[mf][2],a[mf][3],  \
                            b[nf][0], b[nf][1]);                               \
        }                                                                      \
    }

// ---------------------------------------------------------------------------
// Fused QKV projection (fp16 inputs). grid (36, 32): x/12 sel, x%12 head.
// ---------------------------------------------------------------------------
__global__ __launch_bounds__(256)
void gemm_qkv_kernel(const __half* __restrict__ A,
                     const __half* __restrict__ Wq, const __half* __restrict__ Wk,
                     const __half* __restrict__ Wv,
                     const float* __restrict__ bq, const float* __restrict__ bk,
                     const float* __restrict__ bv)
{
    extern __shared__ __half gsmh[];
    const unsigned sbase = (unsigned)__cvta_generic_to_shared(gsmh);

    const int t    = threadIdx.x;
    const int lane = t & 31;
    const int wid  = t >> 5;
    const int wm   = (wid & 3) * 32;
    const int wn   = (wid >> 2) * 32;
    const int mtile = blockIdx.y * 128;
    const int sel  = blockIdx.x / 12;
    const int head = blockIdx.x % 12;
    const int ntile = head * 64;
    const int r = lane >> 2, c = lane & 3;

    const __half* W   = (sel == 0) ? Wq : (sel == 1) ? Wk : Wv;
    const float* bias = (sel == 0) ? bq : (sel == 1) ? bk : bv;

    GEMM_MAINLOOP_H(A, W)

    const float scale = (sel == 0) ? QSCALE : 1.0f;
#pragma unroll
    for (int mf = 0; mf < 2; mf++) {
#pragma unroll
        for (int nf = 0; nf < 4; nf++) {
            int row = mtile + wm + mf * 16 + r;
            int col = wn + nf * 8 + 2 * c;
            float bx = bias[ntile + col], by = bias[ntile + col + 1];
            float v00 = (acc[mf][nf].x + bx) * scale;
            float v01 = (acc[mf][nf].y + by) * scale;
            float v10 = (acc[mf][nf].z + bx) * scale;
            float v11 = (acc[mf][nf].w + by) * scale;
            if (sel < 2) {
                __half* o = (sel == 0 ? g_q : g_k) + (size_t)head * SEQ * HD;
                *(__half2*)(o + (size_t)row * HD + col) = __floats2half2_rn(v00, v01);
                *(__half2*)(o + (size_t)(row + 8) * HD + col) = __floats2half2_rn(v10, v11);
            } else {
                __half* o = g_v + (size_t)head * SEQ * HD;
                size_t b0 = (size_t)(row >> 6) * (HD * 64) + (row & 63);
                size_t b1 = (size_t)((row + 8) >> 6) * (HD * 64) + ((row + 8) & 63);
                o[b0 + (size_t)col * 64]       = __float2half_rn(v00);
                o[b0 + (size_t)(col + 1) * 64] = __float2half_rn(v01);
                o[b1 + (size_t)col * 64]       = __float2half_rn(v10);
                o[b1 + (size_t)(col + 1) * 64] = __float2half_rn(v11);
            }
        }
    }
}

// ---------------------------------------------------------------------------
// Output projection (A = g_att fp16) -> fp32 out
// ---------------------------------------------------------------------------
__global__ __launch_bounds__(256)
void gemm_o_kernel(const __half* __restrict__ A, const __half* __restrict__ W,
                   const float* __restrict__ bias, float* __restrict__ out)
{
    extern __shared__ __half gsmh[];
    const unsigned sbase = (unsigned)__cvta_generic_to_shared(gsmh);

    const int t    = threadIdx.x;
    const int lane = t & 31;
    const int wid  = t >> 5;
    const int wm   = (wid & 3) * 32;
    const int wn   = (wid >> 2) * 32;
    const int mtile = blockIdx.y * 128;
    const int ntile = blockIdx.x * 64;
    const int r = lane >> 2, c = lane & 3;

    GEMM_MAINLOOP_H(A, W)

#pragma unroll
    for (int mf = 0; mf < 2; mf++) {
#pragma unroll
        for (int nf = 0; nf < 4; nf++) {
            int row = mtile + wm + mf * 16 + r;
            int col = wn + nf * 8 + 2 * c;
            float bx = bias[ntile + col], by = bias[ntile + col + 1];
            *(float2*)(out + (size_t)row * CDIM + ntile + col) =
                make_float2(acc[mf][nf].x + bx, acc[mf][nf].y + by);
            *(float2*)(out + (size_t)(row + 8) * CDIM + ntile + col) =
                make_float2(acc[mf][nf].z + bx, acc[mf][nf].w + by);
        }
    }
}

// ---------------------------------------------------------------------------
// rel bias, fp16 tensor cores (unchanged).
// ---------------------------------------------------------------------------
#define REL_SMEM ((64*72 + 64*72 + 128*72) * 2)

__global__ __launch_bounds__(128)
void rel_tc_kernel(const float* __restrict__ rel_pos_h,
                   const float* __restrict__ rel_pos_w)
{
    extern __shared__ char relsm[];
    __half* Qs  = (__half*)relsm;
    __half* Rhs = Qs + 64 * 72;
    __half* Rws = Rhs + 64 * 72;
    float*  Gs  = (float*)relsm;

    const int qh   = blockIdx.x;
    const int head = blockIdx.y;
    const int t    = threadIdx.x;
    const int lane = t & 31;
    const int wid  = t >> 5;
    const int r = lane >> 2, c = lane & 3;
    const int wr = wid * 16;

    const __half* qbase = g_q + ((size_t)head * SEQ + (size_t)qh * 64) * HD;
#pragma unroll
    for (int i = 0; i < 4; i++) {
        int lin = t + i * 128, row = lin >> 3, c8 = (lin & 7) * 8;
        *(uint4*)(Qs + row * 72 + c8) = *(const uint4*)(qbase + lin * 8);
    }
#pragma unroll
    for (int i = 0; i < 8; i++) {
        int lin = t + i * 128, row = lin >> 4, c4 = (lin & 15) * 4;
        float4 v = *(const float4*)(rel_pos_h + (size_t)(qh - row + 63) * HD + c4);
        *(uint2*)(Rhs + row * 72 + c4) =
            make_uint2(h2u(8.f*v.x, 8.f*v.y), h2u(8.f*v.z, 8.f*v.w));
    }
#pragma unroll
    for (int i = 0; i < 16; i++) {
        int lin = t + i * 128, row = lin >> 4, c4 = (lin & 15) * 4;
        float4 v = make_float4(0.f, 0.f, 0.f, 0.f);
        if (row < 127) v = *(const float4*)(rel_pos_w + (size_t)row * HD + c4);
        *(uint2*)(Rws + row * 72 + c4) =
            make_uint2(h2u(8.f*v.x, 8.f*v.y), h2u(8.f*v.z, 8.f*v.w));
    }
    __syncthreads();

    float4 sv[8], gv[16];
#pragma unroll
    for (int i = 0; i < 8; i++)  sv[i] = make_float4(0.f,0.f,0.f,0.f);
#pragma unroll
    for (int i = 0; i < 16; i++) gv[i] = make_float4(0.f,0.f,0.f,0.f);

    const int row0 = wr + r, row1 = row0 + 8;
#pragma unroll
    for (int ks = 0; ks < 4; ks++) {
        int kb = ks * 16;
        unsigned a0 = ldu(&Qs[row0 * 72 + kb + 2*c]);
        unsigned a1 = ldu(&Qs[row1 * 72 + kb + 2*c]);
        unsigned a2 = ldu(&Qs[row0 * 72 + kb + 2*c + 8]);
        unsigned a3 = ldu(&Qs[row1 * 72 + kb + 2*c + 8]);
#pragma unroll
        for (int nf = 0; nf < 8; nf++) {
            unsigned b0 = ldu(&Rhs[(nf*8+r) * 72 + kb + 2*c]);
            unsigned b1 = ldu(&Rhs[(nf*8+r) * 72 + kb + 2*c + 8]);
            mma_f16(sv[nf], a0, a1, a2, a3, b0, b1);
        }
#pragma unroll
        for (int nf = 0; nf < 16; nf++) {
            unsigned b0 = ldu(&Rws[(nf*8+r) * 72 + kb + 2*c]);
            unsigned b1 = ldu(&Rws[(nf*8+r) * 72 + kb + 2*c + 8]);
            mma_f16(gv[nf], a0, a1, a2, a3, b0, b1);
        }
    }

    float* hb = g_relh + ((size_t)head * SEQ + (size_t)qh * 64) * 64;
#pragma unroll
    for (int nf = 0; nf < 8; nf++) {
        int col = nf * 8 + 2 * c;
        *(float2*)(hb + (size_t)row0 * 64 + col) = make_float2(sv[nf].x, sv[nf].y);
        *(float2*)(hb + (size_t)row1 * 64 + col) = make_float2(sv[nf].z, sv[nf].w);
    }

    __syncthreads();
#pragma unroll
    for (int nf = 0; nf < 16; nf++) {
        int col = nf * 8 + 2 * c;
        *(float2*)(Gs + row0 * 132 + col) = make_float2(gv[nf].x, gv[nf].y);
        *(float2*)(Gs + row1 * 132 + col) = make_float2(gv[nf].z, gv[nf].w);
    }
    __syncthreads();

    float* wb = g_relw + ((size_t)head * SEQ + (size_t)qh * 64) * 64;
    int grow = t >> 1, kw0 = (t & 1) * 32;
#pragma unroll
    for (int kw = 0; kw < 32; kw++) {
        wb[(size_t)grow * 64 + kw0 + kw] = Gs[grow * 132 + grow - (kw0 + kw) + 63];
    }
}

// ---------------------------------------------------------------------------
// fp16 flash attention, software-pipelined: PV(kc-1) interleaved with QK(kc).
// 8 warps x 16 query rows, 256 threads, 4-stage cp.async (V of prev chunk must
// survive the prefetch), ldmatrix B-frags, half2 softmax, ones-MMA row sums.
// ---------------------------------------------------------------------------
#define AT_STAGE 18432
#define ATTN_SMEM (4 * AT_STAGE)   // 73728 B

__global__ __launch_bounds__(256, 2)
void attn_tc_kernel()
{
    extern __shared__ __half smh[];
    const unsigned sbase = (unsigned)__cvta_generic_to_shared(smh);

    const int t    = threadIdx.x;
    const int lane = t & 31;
    const int wid  = t >> 5;          // 0..7
    const int qt   = blockIdx.x;
    const int head = blockIdx.y;
    const int r = lane >> 2, c = lane & 3;
    const int row0 = wid * 16 + r, row1 = row0 + 8;

    const unsigned lmb =
        ((((lane >> 4) & 1) * 8 + (lane & 7)) * 72 + ((lane >> 3) & 1) * 8) * 2;

    const __half* kbase = g_k + (size_t)head * SEQ * HD;
    const __half* vbase = g_v + (size_t)head * SEQ * HD;

    // ---- issue chunks 0,1 into stages 0,1 ----
#pragma unroll
    for (int s = 0; s < 2; s++) {
        const __half* kp = kbase + (size_t)s * 64 * HD;
        const __half* vp = vbase + (size_t)s * 64 * HD;
#pragma unroll
        for (int i = 0; i < 2; i++) {
            int seg = t + i * 256, row = seg >> 3, c8 = (seg & 7) * 8;
            CP16(sbase + s * AT_STAGE + (row * 72 + c8) * 2, kp + seg * 8);
            CP16(sbase + s * AT_STAGE + 9216 + (row * 72 + c8) * 2, vp + seg * 8);
        }
        CP_COMMIT();
    }

    // ---- Q fragments ----
    const __half* qb = g_q + ((size_t)head * SEQ + (size_t)qt * 128) * HD;
    unsigned qa[4][4];
#pragma unroll
    for (int ks = 0; ks < 4; ks++) {
        int kb = ks * 16;
        qa[ks][0] = ldu(qb + (size_t)row0 * HD + kb + 2*c);
        qa[ks][1] = ldu(qb + (size_t)row1 * HD + kb + 2*c);
        qa[ks][2] = ldu(qb + (size_t)row0 * HD + kb + 2*c + 8);
        qa[ks][3] = ldu(qb + (size_t)row1 * HD + kb + 2*c + 8);
    }

    // ---- rel_w bias as half2 ----
    const float* rwb = g_relw + ((size_t)head * SEQ + (size_t)qt * 128) * 64;
    const float* rhb = g_relh + ((size_t)head * SEQ + (size_t)qt * 128) * 64;
    unsigned rwv[8][2];
#pragma unroll
    for (int nf = 0; nf < 8; nf++) {
        int col = nf * 8 + 2 * c;
        rwv[nf][0] = h2u(__ldg(rwb + (size_t)row0 * 64 + col),
                         __ldg(rwb + (size_t)row0 * 64 + col + 1));
        rwv[nf][1] = h2u(__ldg(rwb + (size_t)row1 * 64 + col),
                         __ldg(rwb + (size_t)row1 * 64 + col + 1));
    }

    float4 O[8];
#pragma unroll
    for (int nf = 0; nf < 8; nf++) O[nf] = make_float4(0.f,0.f,0.f,0.f);
    float4 lacc = make_float4(0.f,0.f,0.f,0.f);
    const unsigned ONESH2 = 0x3C003C00u;
    unsigned p[8][2];

    // ================= prologue: QK(0) + softmax(0) =================
    {
        CP_WAIT1();
        __syncthreads();
        // prefetch chunk 2 -> stage 2
        {
            const __half* kp = kbase + (size_t)2 * 64 * HD;
            const __half* vp = vbase + (size_t)2 * 64 * HD;
#pragma unroll
            for (int i = 0; i < 2; i++) {
                int seg = t + i * 256, row = seg >> 3, c8 = (seg & 7) * 8;
                CP16(sbase + 2 * AT_STAGE + (row * 72 + c8) * 2, kp + seg * 8);
                CP16(sbase + 2 * AT_STAGE + 9216 + (row * 72 + c8) * 2, vp + seg * 8);
            }
            CP_COMMIT();
        }
        const unsigned kaddr = sbase + lmb;   // stage 0
        float4 sv[8];
#pragma unroll
        for (int nf = 0; nf < 8; nf++) sv[nf] = make_float4(0.f,0.f,0.f,0.f);
#pragma unroll
        for (int ks = 0; ks < 4; ks++)
#pragma unroll
            for (int p4 = 0; p4 < 4; p4++) {
                unsigned b00, b01, b10, b11;
                LDSM4(b00, b01, b10, b11, kaddr + p4 * 2304 + ks * 32);
                mma_f16(sv[2*p4],   qa[ks][0], qa[ks][1], qa[ks][2], qa[ks][3], b00, b01);
                mma_f16(sv[2*p4+1], qa[ks][0], qa[ks][1], qa[ks][2], qa[ks][3], b10, b11);
            }
        float rh0 = __ldg(rhb + (size_t)row0 * 64 + 0);
        float rh1 = __ldg(rhb + (size_t)row1 * 64 + 0);
        unsigned rhh0 = h2u(rh0, rh0), rhh1 = h2u(rh1, rh1);
#pragma unroll
        for (int nf = 0; nf < 8; nf++) {
            p[nf][0] = ex2h2(hadd2(h2u(sv[nf].x, sv[nf].y), hadd2(rwv[nf][0], rhh0)));
            p[nf][1] = ex2h2(hadd2(h2u(sv[nf].z, sv[nf].w), hadd2(rwv[nf][1], rhh1)));
        }
    }

    // ================= main loop: fused QK(kc) + PV(kc-1) =================
    for (int kc = 1; kc < 64; kc++) {
        if (kc == 63) { CP_WAIT0(); } else { CP_WAIT1(); }
        __syncthreads();

        if (kc + 2 < 64) {
            const int sd = (kc + 2) & 3;
            const __half* kp = kbase + (size_t)(kc + 2) * 64 * HD;
            const __half* vp = vbase + (size_t)(kc + 2) * 64 * HD;
#pragma unroll
            for (int i = 0; i < 2; i++) {
                int seg = t + i * 256, row = seg >> 3, c8 = (seg & 7) * 8;
                CP16(sbase + sd * AT_STAGE + (row * 72 + c8) * 2, kp + seg * 8);
                CP16(sbase + sd * AT_STAGE + 9216 + (row * 72 + c8) * 2, vp + seg * 8);
            }
            CP_COMMIT();
        }

        const unsigned kaddr = sbase + (kc & 3) * AT_STAGE + lmb;          // K(kc)
        const unsigned vaddr = sbase + ((kc - 1) & 3) * AT_STAGE + 9216 + lmb; // V(kc-1)

        float4 sv[8];
#pragma unroll
        for (int nf = 0; nf < 8; nf++) sv[nf] = make_float4(0.f,0.f,0.f,0.f);

#pragma unroll
        for (int ks = 0; ks < 4; ks++) {
            // QK group (chunk kc)
#pragma unroll
            for (int p4 = 0; p4 < 4; p4++) {
                unsigned b00, b01, b10, b11;
                LDSM4(b00, b01, b10, b11, kaddr + p4 * 2304 + ks * 32);
                mma_f16(sv[2*p4],   qa[ks][0], qa[ks][1], qa[ks][2], qa[ks][3], b00, b01);
                mma_f16(sv[2*p4+1], qa[ks][0], qa[ks][1], qa[ks][2], qa[ks][3], b10, b11);
            }
            // PV group (chunk kc-1) — independent, fills softmax/MMA latency
            unsigned a0 = p[2*ks][0], a1 = p[2*ks][1];
            unsigned a2 = p[2*ks+1][0], a3 = p[2*ks+1][1];
#pragma unroll
            for (int p4 = 0; p4 < 4; p4++) {
                unsigned v00, v01, v10, v11;
                LDSM4(v00, v01, v10, v11, vaddr + p4 * 2304 + ks * 32);
                mma_f16(O[2*p4],   a0, a1, a2, a3, v00, v01);
                mma_f16(O[2*p4+1], a0, a1, a2, a3, v10, v11);
            }
            mma_f16(lacc, a0, a1, a2, a3, ONESH2, ONESH2);
        }

        // softmax(kc) -> p
        float rh0 = __ldg(rhb + (size_t)row0 * 64 + kc);
        float rh1 = __ldg(rhb + (size_t)row1 * 64 + kc);
        unsigned rhh0 = h2u(rh0, rh0), rhh1 = h2u(rh1, rh1);
#pragma unroll
        for (int nf = 0; nf < 8; nf++) {
            p[nf][0] = ex2h2(hadd2(h2u(sv[nf].x, sv[nf].y), hadd2(rwv[nf][0], rhh0)));
            p[nf][1] = ex2h2(hadd2(h2u(sv[nf].z, sv[nf].w), hadd2(rwv[nf][1], rhh1)));
        }
    }

    // ================= epilogue: PV(63) =================
    {
        const unsigned vaddr = sbase + (63 & 3) * AT_STAGE + 9216 + lmb;
#pragma unroll
        for (int ks = 0; ks < 4; ks++) {
            unsigned a0 = p[2*ks][0], a1 = p[2*ks][1];
            unsigned a2 = p[2*ks+1][0], a3 = p[2*ks+1][1];
#pragma unroll
            for (int p4 = 0; p4 < 4; p4++) {
                unsigned v00, v01, v10, v11;
                LDSM4(v00, v01, v10, v11, vaddr + p4 * 2304 + ks * 32);
                mma_f16(O[2*p4],   a0, a1, a2, a3, v00, v01);
                mma_f16(O[2*p4+1], a0, a1, a2, a3, v10, v11);
            }
            mma_f16(lacc, a0, a1, a2, a3, ONESH2, ONESH2);
        }
    }

    // ---- normalize (l from ones-MMA), store fp16 ----
    float inv0 = 1.f / lacc.x, inv1 = 1.f / lacc.z;
    __half* ob = g_att + (size_t)(qt * 128) * CDIM + head * HD;
#pragma unroll
    for (int nf = 0; nf < 8; nf++) {
        int col = nf * 8 + 2 * c;
        *(__half2*)(ob + (size_t)row0 * CDIM + col) =
            __floats2half2_rn(O[nf].x * inv0, O[nf].y * inv0);
        *(__half2*)(ob + (size_t)row1 * CDIM + col) =
            __floats2half2_rn(O[nf].z * inv1, O[nf].w * inv1);
    }
}

// ---------------------------------------------------------------------------
extern "C" void kernel_launch(void* const* d_in, const int* in_sizes, int n_in,
                              void* d_out, int out_size)
{
    const float* hs  = (const float*)d_in[0];
    const float* w_q = (const float*)d_in[1];
    const float* b_q = (const float*)d_in[2];
    const float* w_k = (const float*)d_in[3];
    const float* b_k = (const float*)d_in[4];
    const float* w_v = (const float*)d_in[5];
    const float* b_v = (const float*)d_in[6];
    const float* w_o = (const float*)d_in[7];
    const float* b_o = (const float*)d_in[8];
    const float* rph = (const float*)d_in[9];
    const float* rpw = (const float*)d_in[10];
    float* out = (float*)d_out;

    __half *hsp, *wqp, *wkp, *wvp, *wop, *atp;
    cudaGetSymbolAddress((void**)&hsp, g_hs);
    cudaGetSymbolAddress((void**)&wqp, g_wq);
    cudaGetSymbolAddress((void**)&wkp, g_wk);
    cudaGetSymbolAddress((void**)&wvp, g_wv);
    cudaGetSymbolAddress((void**)&wop, g_wo);
    cudaGetSymbolAddress((void**)&atp, g_att);

    cudaFuncSetAttribute(gemm_qkv_kernel, cudaFuncAttributeMaxDynamicSharedMemorySize, GEMM_SMEM);
    cudaFuncSetAttribute(gemm_o_kernel,   cudaFuncAttributeMaxDynamicSharedMemorySize, GEMM_SMEM);
    cudaFuncSetAttribute(rel_tc_kernel,   cudaFuncAttributeMaxDynamicSharedMemorySize, REL_SMEM);
    cudaFuncSetAttribute(attn_tc_kernel,  cudaFuncAttributeMaxDynamicSharedMemorySize, ATTN_SMEM);

    const int NG = NG_HS + 4 * NG_W;
    cvt5_kernel<<<(NG + 255) / 256, 256>>>(hs, w_q, w_k, w_v, w_o);
    gemm_qkv_kernel<<<dim3(36, SEQ/128), 256, GEMM_SMEM>>>(hsp, wqp, wkp, wvp, b_q, b_k, b_v);
    rel_tc_kernel<<<dim3(64, NHEAD), 128, REL_SMEM>>>(rph, rpw);
    attn_tc_kernel<<<dim3(SEQ/128, NHEAD), 256, ATTN_SMEM>>>();
    gemm_o_kernel<<<dim3(CDIM/64, SEQ/128), 256, GEMM_SMEM>>>(atp, wop, b_o, out);
}

// round 15
// speedup vs baseline: 1.0455x; 1.0455x over previous
#include <cuda_runtime.h>
#include <cuda_fp16.h>
#include <math.h>

#define SEQ   4096
#define CDIM  768
#define NHEAD 12
#define HD    64

// ---------------- scratch ---------------------------------------------------
__device__ __align__(16) __half g_hs[SEQ * CDIM];
__device__ __align__(16) __half g_wq[CDIM * CDIM];
__device__ __align__(16) __half g_wk[CDIM * CDIM];
__device__ __align__(16) __half g_wv[CDIM * CDIM];
__device__ __align__(16) __half g_wo[CDIM * CDIM];
__device__ __align__(16) __half g_q[NHEAD * SEQ * HD];   // fp16, pre-scaled 0.125*log2e
__device__ __align__(16) __half g_k[NHEAD * SEQ * HD];   // fp16 [head][s][d]
__device__ __align__(16) __half g_v[NHEAD * SEQ * HD];   // fp16 [head][s/64][d][s%64]
__device__ __align__(16) float  g_relh[NHEAD * SEQ * 64];  // log2-domain
__device__ __align__(16) float  g_relw[NHEAD * SEQ * 64];  // log2-domain
__device__ __align__(16) __half g_att[SEQ * CDIM];       // attention out (fp16)

#define QSCALE 0.18033688011112042f   /* 0.125 * log2(e) */

// ---------------- helpers ---------------------------------------------------
__device__ __forceinline__ unsigned h2u(float a, float b) {
    __half2 h = __floats2half2_rn(a, b);
    return *(unsigned*)&h;
}
__device__ __forceinline__ unsigned hadd2(unsigned a, unsigned b) {
    unsigned d; asm("add.f16x2 %0, %1, %2;" : "=r"(d) : "r"(a), "r"(b)); return d;
}
__device__ __forceinline__ unsigned ex2h2(unsigned x) {
    unsigned y; asm("ex2.approx.f16x2 %0, %1;" : "=r"(y) : "r"(x)); return y;
}
__device__ __forceinline__ void mma_f16(float4& d,
    unsigned a0, unsigned a1, unsigned a2, unsigned a3,
    unsigned b0, unsigned b1)
{
    asm volatile(
        "mma.sync.aligned.m16n8k16.row.col.f32.f16.f16.f32 "
        "{%0,%1,%2,%3},{%4,%5,%6,%7},{%8,%9},{%0,%1,%2,%3};"
        : "+f"(d.x), "+f"(d.y), "+f"(d.z), "+f"(d.w)
        : "r"(a0), "r"(a1), "r"(a2), "r"(a3), "r"(b0), "r"(b1));
}
__device__ __forceinline__ unsigned ldu(const __half* p) { return *(const unsigned*)p; }

#define LDSM4(d0,d1,d2,d3,addr) \
    asm volatile("ldmatrix.sync.aligned.m8n8.x4.shared.b16 {%0,%1,%2,%3}, [%4];" \
        : "=r"(d0), "=r"(d1), "=r"(d2), "=r"(d3) : "r"(addr))

#define CP16(dst_u32, src_ptr) \
    asm volatile("cp.async.cg.shared.global [%0], [%1], 16;" :: "r"(dst_u32), "l"(src_ptr))
#define CP_COMMIT()  asm volatile("cp.async.commit_group;")
#define CP_WAIT0()   asm volatile("cp.async.wait_group 0;")
#define CP_WAIT1()   asm volatile("cp.async.wait_group 1;")

// ---------------------------------------------------------------------------
// fp32 -> fp16 conversion of hs + 4 weight matrices (one launch).
// ---------------------------------------------------------------------------
#define NG_HS (SEQ * CDIM / 8)
#define NG_W  (CDIM * CDIM / 8)

__global__ __launch_bounds__(256)
void cvt5_kernel(const float* __restrict__ hs,
                 const float* __restrict__ wq, const float* __restrict__ wk,
                 const float* __restrict__ wv, const float* __restrict__ wo)
{
    int i = blockIdx.x * 256 + threadIdx.x;
    const float* src; __half* dst; int j;
    if (i < NG_HS) { src = hs; dst = g_hs; j = i; }
    else {
        i -= NG_HS;
        int w = i / NG_W; j = i - w * NG_W;
        src = (w == 0) ? wq : (w == 1) ? wk : (w == 2) ? wv : wo;
        dst = (w == 0) ? g_wq : (w == 1) ? g_wk : (w == 2) ? g_wv : g_wo;
    }
    float4 a = ((const float4*)src)[2 * j];
    float4 b = ((const float4*)src)[2 * j + 1];
    uint4 o;
    o.x = h2u(a.x, a.y); o.y = h2u(a.z, a.w);
    o.z = h2u(b.x, b.y); o.w = h2u(b.z, b.w);
    ((uint4*)dst)[j] = o;
}

// ===========================================================================
// fp16 GEMM, 128x128 CTA tile, k-chunk 32, 256 thr = 8 warps (2m x 4n),
// warp tile 64x32 (4 m-frags x 4 n-frags). cp.async double buffer + ldmatrix.
// ===========================================================================
#define G2S (128 * 40)                 // halves per matrix per stage
#define GEMM2_SMEM (4 * G2S * 2)       // 40960 B

#define GEMM2_ISSUE(A_PTR, W_PTR, kc, stage)                                   \
    do {                                                                       \
        _Pragma("unroll")                                                      \
        for (int i_ = 0; i_ < 2; i_++) {                                       \
            int seg = t + i_ * 256, row = seg >> 2, s8 = (seg & 3) * 8;        \
            CP16(sbase + ((stage) * G2S + row * 40 + s8) * 2,                  \
                 A_PTR + (size_t)(mtile + row) * CDIM + (kc) + s8);            \
        }                                                                      \
        _Pragma("unroll")                                                      \
        for (int i_ = 0; i_ < 2; i_++) {                                       \
            int seg = t + i_ * 256, row = seg >> 2, s8 = (seg & 3) * 8;        \
            CP16(sbase + ((2 + (stage)) * G2S + row * 40 + s8) * 2,            \
                 W_PTR + (size_t)(ntile + row) * CDIM + (kc) + s8);            \
        }                                                                      \
        CP_COMMIT();                                                           \
    } while (0)

#define GEMM2_MAINLOOP(A_PTR, W_PTR)                                           \
    float4 acc[4][4];                                                          \
    _Pragma("unroll")                                                          \
    for (int i = 0; i < 4; i++)                                                \
        _Pragma("unroll")                                                      \
        for (int j = 0; j < 4; j++) acc[i][j] = make_float4(0.f,0.f,0.f,0.f);  \
    const unsigned a_lmb =                                                     \
        ((wm + (lane & 15)) * 40 + ((lane >> 4) & 1) * 8) * 2;                 \
    const unsigned b_lmb =                                                     \
        ((wn + (lane & 7) + ((lane >> 4) & 1) * 8) * 40 +                      \
         ((lane >> 3) & 1) * 8) * 2;                                           \
    GEMM2_ISSUE(A_PTR, W_PTR, 0, 0);                                           \
    for (int kci = 0; kci < 24; kci++) {                                       \
        const int cur = kci & 1;                                               \
        CP_WAIT0();                                                            \
        __syncthreads();                                                       \
        if (kci < 23) GEMM2_ISSUE(A_PTR, W_PTR, (kci + 1) * 32, cur ^ 1);      \
        const unsigned aaddr = sbase + cur * (G2S * 2) + a_lmb;                \
        const unsigned baddr = sbase + (2 + cur) * (G2S * 2) + b_lmb;          \
        _Pragma("unroll")                                                      \
        for (int ks = 0; ks < 2; ks++) {                                       \
            unsigned a[4][4], b[4][2];                                         \
            _Pragma("unroll")                                                  \
            for (int mf = 0; mf < 4; mf++)                                     \
                LDSM4(a[mf][0], a[mf][1], a[mf][2], a[mf][3],                  \
                      aaddr + mf * 1280 + ks * 32);                            \
            LDSM4(b[0][0], b[0][1], b[1][0], b[1][1], baddr + ks * 32);        \
            LDSM4(b[2][0], b[2][1], b[3][0], b[3][1], baddr + 1280 + ks * 32); \
            _Pragma("unroll")                                                  \
            for (int mf = 0; mf < 4; mf++)                                     \
                _Pragma("unroll")                                              \
                for (int nf = 0; nf < 4; nf++)                                 \
                    mma_f16(acc[mf][nf], a[mf][0],a[mf][1],a[mf][2],a[mf][3],  \
                            b[nf][0], b[nf][1]);                               \
        }                                                                      \
    }

// ---------------------------------------------------------------------------
// Fused QKV projection. grid (18, 32): x/6 = sel, x%6 = n-tile (128 wide,
// spans 2 heads). Epilogue maps each column to its head.
// ---------------------------------------------------------------------------
__global__ __launch_bounds__(256)
void gemm_qkv_kernel(const __half* __restrict__ A,
                     const __half* __restrict__ Wq, const __half* __restrict__ Wk,
                     const __half* __restrict__ Wv,
                     const float* __restrict__ bq, const float* __restrict__ bk,
                     const float* __restrict__ bv)
{
    extern __shared__ __half gsmh[];
    const unsigned sbase = (unsigned)__cvta_generic_to_shared(gsmh);

    const int t    = threadIdx.x;
    const int lane = t & 31;
    const int wid  = t >> 5;
    const int wm   = (wid & 1) * 64;
    const int wn   = (wid >> 1) * 32;
    const int mtile = blockIdx.y * 128;
    const int sel  = blockIdx.x / 6;
    const int ntile = (blockIdx.x % 6) * 128;
    const int r = lane >> 2, c = lane & 3;

    const __half* W   = (sel == 0) ? Wq : (sel == 1) ? Wk : Wv;
    const float* bias = (sel == 0) ? bq : (sel == 1) ? bk : bv;

    GEMM2_MAINLOOP(A, W)

    const float scale = (sel == 0) ? QSCALE : 1.0f;
#pragma unroll
    for (int mf = 0; mf < 4; mf++) {
#pragma unroll
        for (int nf = 0; nf < 4; nf++) {
            int row = mtile + wm + mf * 16 + r;
            int gcol = ntile + wn + nf * 8 + 2 * c;     // global feature, even
            int head = gcol >> 6, hcol = gcol & 63;
            float bx = bias[gcol], by = bias[gcol + 1];
            float v00 = (acc[mf][nf].x + bx) * scale;
            float v01 = (acc[mf][nf].y + by) * scale;
            float v10 = (acc[mf][nf].z + bx) * scale;
            float v11 = (acc[mf][nf].w + by) * scale;
            if (sel < 2) {
                __half* o = (sel == 0 ? g_q : g_k) + (size_t)head * SEQ * HD;
                *(__half2*)(o + (size_t)row * HD + hcol) = __floats2half2_rn(v00, v01);
                *(__half2*)(o + (size_t)(row + 8) * HD + hcol) = __floats2half2_rn(v10, v11);
            } else {
                __half* o = g_v + (size_t)head * SEQ * HD;
                size_t b0 = (size_t)(row >> 6) * (HD * 64) + (row & 63);
                size_t b1 = (size_t)((row + 8) >> 6) * (HD * 64) + ((row + 8) & 63);
                o[b0 + (size_t)hcol * 64]       = __float2half_rn(v00);
                o[b0 + (size_t)(hcol + 1) * 64] = __float2half_rn(v01);
                o[b1 + (size_t)hcol * 64]       = __float2half_rn(v10);
                o[b1 + (size_t)(hcol + 1) * 64] = __float2half_rn(v11);
            }
        }
    }
}

// ---------------------------------------------------------------------------
// Output projection (A = g_att fp16) -> fp32 out. grid (6, 32).
// ---------------------------------------------------------------------------
__global__ __launch_bounds__(256)
void gemm_o_kernel(const __half* __restrict__ A, const __half* __restrict__ W,
                   const float* __restrict__ bias, float* __restrict__ out)
{
    extern __shared__ __half gsmh[];
    const unsigned sbase = (unsigned)__cvta_generic_to_shared(gsmh);

    const int t    = threadIdx.x;
    const int lane = t & 31;
    const int wid  = t >> 5;
    const int wm   = (wid & 1) * 64;
    const int wn   = (wid >> 1) * 32;
    const int mtile = blockIdx.y * 128;
    const int ntile = blockIdx.x * 128;
    const int r = lane >> 2, c = lane & 3;

    GEMM2_MAINLOOP(A, W)

#pragma unroll
    for (int mf = 0; mf < 4; mf++) {
#pragma unroll
        for (int nf = 0; nf < 4; nf++) {
            int row = mtile + wm + mf * 16 + r;
            int gcol = ntile + wn + nf * 8 + 2 * c;
            float bx = bias[gcol], by = bias[gcol + 1];
            *(float2*)(out + (size_t)row * CDIM + gcol) =
                make_float2(acc[mf][nf].x + bx, acc[mf][nf].y + by);
            *(float2*)(out + (size_t)(row + 8) * CDIM + gcol) =
                make_float2(acc[mf][nf].z + bx, acc[mf][nf].w + by);
        }
    }
}

// ---------------------------------------------------------------------------
// rel bias, fp16 tensor cores (unchanged).
// ---------------------------------------------------------------------------
#define REL_SMEM ((64*72 + 64*72 + 128*72) * 2)

__global__ __launch_bounds__(128)
void rel_tc_kernel(const float* __restrict__ rel_pos_h,
                   const float* __restrict__ rel_pos_w)
{
    extern __shared__ char relsm[];
    __half* Qs  = (__half*)relsm;
    __half* Rhs = Qs + 64 * 72;
    __half* Rws = Rhs + 64 * 72;
    float*  Gs  = (float*)relsm;

    const int qh   = blockIdx.x;
    const int head = blockIdx.y;
    const int t    = threadIdx.x;
    const int lane = t & 31;
    const int wid  = t >> 5;
    const int r = lane >> 2, c = lane & 3;
    const int wr = wid * 16;

    const __half* qbase = g_q + ((size_t)head * SEQ + (size_t)qh * 64) * HD;
#pragma unroll
    for (int i = 0; i < 4; i++) {
        int lin = t + i * 128, row = lin >> 3, c8 = (lin & 7) * 8;
        *(uint4*)(Qs + row * 72 + c8) = *(const uint4*)(qbase + lin * 8);
    }
#pragma unroll
    for (int i = 0; i < 8; i++) {
        int lin = t + i * 128, row = lin >> 4, c4 = (lin & 15) * 4;
        float4 v = *(const float4*)(rel_pos_h + (size_t)(qh - row + 63) * HD + c4);
        *(uint2*)(Rhs + row * 72 + c4) =
            make_uint2(h2u(8.f*v.x, 8.f*v.y), h2u(8.f*v.z, 8.f*v.w));
    }
#pragma unroll
    for (int i = 0; i < 16; i++) {
        int lin = t + i * 128, row = lin >> 4, c4 = (lin & 15) * 4;
        float4 v = make_float4(0.f, 0.f, 0.f, 0.f);
        if (row < 127) v = *(const float4*)(rel_pos_w + (size_t)row * HD + c4);
        *(uint2*)(Rws + row * 72 + c4) =
            make_uint2(h2u(8.f*v.x, 8.f*v.y), h2u(8.f*v.z, 8.f*v.w));
    }
    __syncthreads();

    float4 sv[8], gv[16];
#pragma unroll
    for (int i = 0; i < 8; i++)  sv[i] = make_float4(0.f,0.f,0.f,0.f);
#pragma unroll
    for (int i = 0; i < 16; i++) gv[i] = make_float4(0.f,0.f,0.f,0.f);

    const int row0 = wr + r, row1 = row0 + 8;
#pragma unroll
    for (int ks = 0; ks < 4; ks++) {
        int kb = ks * 16;
        unsigned a0 = ldu(&Qs[row0 * 72 + kb + 2*c]);
        unsigned a1 = ldu(&Qs[row1 * 72 + kb + 2*c]);
        unsigned a2 = ldu(&Qs[row0 * 72 + kb + 2*c + 8]);
        unsigned a3 = ldu(&Qs[row1 * 72 + kb + 2*c + 8]);
#pragma unroll
        for (int nf = 0; nf < 8; nf++) {
            unsigned b0 = ldu(&Rhs[(nf*8+r) * 72 + kb + 2*c]);
            unsigned b1 = ldu(&Rhs[(nf*8+r) * 72 + kb + 2*c + 8]);
            mma_f16(sv[nf], a0, a1, a2, a3, b0, b1);
        }
#pragma unroll
        for (int nf = 0; nf < 16; nf++) {
            unsigned b0 = ldu(&Rws[(nf*8+r) * 72 + kb + 2*c]);
            unsigned b1 = ldu(&Rws[(nf*8+r) * 72 + kb + 2*c + 8]);
            mma_f16(gv[nf], a0, a1, a2, a3, b0, b1);
        }
    }

    float* hb = g_relh + ((size_t)head * SEQ + (size_t)qh * 64) * 64;
#pragma unroll
    for (int nf = 0; nf < 8; nf++) {
        int col = nf * 8 + 2 * c;
        *(float2*)(hb + (size_t)row0 * 64 + col) = make_float2(sv[nf].x, sv[nf].y);
        *(float2*)(hb + (size_t)row1 * 64 + col) = make_float2(sv[nf].z, sv[nf].w);
    }

    __syncthreads();
#pragma unroll
    for (int nf = 0; nf < 16; nf++) {
        int col = nf * 8 + 2 * c;
        *(float2*)(Gs + row0 * 132 + col) = make_float2(gv[nf].x, gv[nf].y);
        *(float2*)(Gs + row1 * 132 + col) = make_float2(gv[nf].z, gv[nf].w);
    }
    __syncthreads();

    float* wb = g_relw + ((size_t)head * SEQ + (size_t)qh * 64) * 64;
    int grow = t >> 1, kw0 = (t & 1) * 32;
#pragma unroll
    for (int kw = 0; kw < 32; kw++) {
        wb[(size_t)grow * 64 + kw0 + kw] = Gs[grow * 132 + grow - (kw0 + kw) + 63];
    }
}

// ---------------------------------------------------------------------------
// fp16 flash attention (exact R11): 8 warps x 16 query rows, 256 threads,
// ldmatrix B-frags, ones-MMA row sums, 3-stage cp.async, half2 softmax.
// ---------------------------------------------------------------------------
#define AT_STAGE 18432
#define ATTN_SMEM (3 * AT_STAGE)   // 55296 B

__global__ __launch_bounds__(256, 2)
void attn_tc_kernel()
{
    extern __shared__ __half smh[];
    const unsigned sbase = (unsigned)__cvta_generic_to_shared(smh);

    const int t    = threadIdx.x;
    const int lane = t & 31;
    const int wid  = t >> 5;          // 0..7
    const int qt   = blockIdx.x;
    const int head = blockIdx.y;
    const int r = lane >> 2, c = lane & 3;
    const int row0 = wid * 16 + r, row1 = row0 + 8;

    const unsigned lmb =
        ((((lane >> 4) & 1) * 8 + (lane & 7)) * 72 + ((lane >> 3) & 1) * 8) * 2;

    const __half* kbase = g_k + (size_t)head * SEQ * HD;
    const __half* vbase = g_v + (size_t)head * SEQ * HD;

    // ---- issue chunks 0,1 ----
#pragma unroll
    for (int s = 0; s < 2; s++) {
        const __half* kp = kbase + (size_t)s * 64 * HD;
        const __half* vp = vbase + (size_t)s * 64 * HD;
#pragma unroll
        for (int i = 0; i < 2; i++) {
            int seg = t + i * 256, row = seg >> 3, c8 = (seg & 7) * 8;
            CP16(sbase + s * AT_STAGE + (row * 72 + c8) * 2, kp + seg * 8);
            CP16(sbase + s * AT_STAGE + 9216 + (row * 72 + c8) * 2, vp + seg * 8);
        }
        CP_COMMIT();
    }

    // ---- Q fragments ----
    const __half* qb = g_q + ((size_t)head * SEQ + (size_t)qt * 128) * HD;
    unsigned qa[4][4];
#pragma unroll
    for (int ks = 0; ks < 4; ks++) {
        int kb = ks * 16;
        qa[ks][0] = ldu(qb + (size_t)row0 * HD + kb + 2*c);
        qa[ks][1] = ldu(qb + (size_t)row1 * HD + kb + 2*c);
        qa[ks][2] = ldu(qb + (size_t)row0 * HD + kb + 2*c + 8);
        qa[ks][3] = ldu(qb + (size_t)row1 * HD + kb + 2*c + 8);
    }

    // ---- rel_w bias as half2 ----
    const float* rwb = g_relw + ((size_t)head * SEQ + (size_t)qt * 128) * 64;
    const float* rhb = g_relh + ((size_t)head * SEQ + (size_t)qt * 128) * 64;
    unsigned rwv[8][2];
#pragma unroll
    for (int nf = 0; nf < 8; nf++) {
        int col = nf * 8 + 2 * c;
        rwv[nf][0] = h2u(__ldg(rwb + (size_t)row0 * 64 + col),
                         __ldg(rwb + (size_t)row0 * 64 + col + 1));
        rwv[nf][1] = h2u(__ldg(rwb + (size_t)row1 * 64 + col),
                         __ldg(rwb + (size_t)row1 * 64 + col + 1));
    }

    float4 O[8];
#pragma unroll
    for (int nf = 0; nf < 8; nf++) O[nf] = make_float4(0.f,0.f,0.f,0.f);
    float4 lacc = make_float4(0.f,0.f,0.f,0.f);
    const unsigned ONESH2 = 0x3C003C00u;

    for (int kc = 0; kc < 64; kc++) {
        if (kc == 63) { CP_WAIT0(); } else { CP_WAIT1(); }
        __syncthreads();

        if (kc + 2 < 64) {
            const int sd = (kc + 2) % 3;
            const __half* kp = kbase + (size_t)(kc + 2) * 64 * HD;
            const __half* vp = vbase + (size_t)(kc + 2) * 64 * HD;
#pragma unroll
            for (int i = 0; i < 2; i++) {
                int seg = t + i * 256, row = seg >> 3, c8 = (seg & 7) * 8;
                CP16(sbase + sd * AT_STAGE + (row * 72 + c8) * 2, kp + seg * 8);
                CP16(sbase + sd * AT_STAGE + 9216 + (row * 72 + c8) * 2, vp + seg * 8);
            }
            CP_COMMIT();
        }

        const unsigned kaddr = sbase + (kc % 3) * AT_STAGE + lmb;
        const unsigned vaddr = kaddr + 9216;

        // ---- S = Q K^T (fp32 accum, zero-init) ----
        float4 sv[8];
#pragma unroll
        for (int nf = 0; nf < 8; nf++) sv[nf] = make_float4(0.f,0.f,0.f,0.f);
#pragma unroll
        for (int ks = 0; ks < 4; ks++) {
#pragma unroll
            for (int p4 = 0; p4 < 4; p4++) {
                unsigned b00, b01, b10, b11;
                LDSM4(b00, b01, b10, b11, kaddr + p4 * 2304 + ks * 32);
                mma_f16(sv[2*p4],   qa[ks][0], qa[ks][1], qa[ks][2], qa[ks][3], b00, b01);
                mma_f16(sv[2*p4+1], qa[ks][0], qa[ks][1], qa[ks][2], qa[ks][3], b10, b11);
            }
        }

        // ---- half2 softmax: S16 = pack(S) + (rw + rh); p = 2^S16 ----
        float rh0 = __ldg(rhb + (size_t)row0 * 64 + kc);
        float rh1 = __ldg(rhb + (size_t)row1 * 64 + kc);
        unsigned rhh0 = h2u(rh0, rh0), rhh1 = h2u(rh1, rh1);
        unsigned p[8][2];
#pragma unroll
        for (int nf = 0; nf < 8; nf++) {
            unsigned s0 = hadd2(h2u(sv[nf].x, sv[nf].y), hadd2(rwv[nf][0], rhh0));
            unsigned s1 = hadd2(h2u(sv[nf].z, sv[nf].w), hadd2(rwv[nf][1], rhh1));
            p[nf][0] = ex2h2(s0);
            p[nf][1] = ex2h2(s1);
        }

        // ---- O += P V ; l += P * ones ----
#pragma unroll
        for (int ks = 0; ks < 4; ks++) {
            unsigned a0 = p[2*ks][0], a1 = p[2*ks][1];
            unsigned a2 = p[2*ks+1][0], a3 = p[2*ks+1][1];
#pragma unroll
            for (int p4 = 0; p4 < 4; p4++) {
                unsigned v00, v01, v10, v11;
                LDSM4(v00, v01, v10, v11, vaddr + p4 * 2304 + ks * 32);
                mma_f16(O[2*p4],   a0, a1, a2, a3, v00, v01);
                mma_f16(O[2*p4+1], a0, a1, a2, a3, v10, v11);
            }
            mma_f16(lacc, a0, a1, a2, a3, ONESH2, ONESH2);
        }
    }

    // ---- epilogue: normalize (l from ones-MMA), store fp16 ----
    float inv0 = 1.f / lacc.x, inv1 = 1.f / lacc.z;
    __half* ob = g_att + (size_t)(qt * 128) * CDIM + head * HD;
#pragma unroll
    for (int nf = 0; nf < 8; nf++) {
        int col = nf * 8 + 2 * c;
        *(__half2*)(ob + (size_t)row0 * CDIM + col) =
            __floats2half2_rn(O[nf].x * inv0, O[nf].y * inv0);
        *(__half2*)(ob + (size_t)row1 * CDIM + col) =
            __floats2half2_rn(O[nf].z * inv1, O[nf].w * inv1);
    }
}

// ---------------------------------------------------------------------------
extern "C" void kernel_launch(void* const* d_in, const int* in_sizes, int n_in,
                              void* d_out, int out_size)
{
    const float* hs  = (const float*)d_in[0];
    const float* w_q = (const float*)d_in[1];
    const float* b_q = (const float*)d_in[2];
    const float* w_k = (const float*)d_in[3];
    const float* b_k = (const float*)d_in[4];
    const float* w_v = (const float*)d_in[5];
    const float* b_v = (const float*)d_in[6];
    const float* w_o = (const float*)d_in[7];
    const float* b_o = (const float*)d_in[8];
    const float* rph = (const float*)d_in[9];
    const float* rpw = (const float*)d_in[10];
    float* out = (float*)d_out;

    __half *hsp, *wqp, *wkp, *wvp, *wop, *atp;
    cudaGetSymbolAddress((void**)&hsp, g_hs);
    cudaGetSymbolAddress((void**)&wqp, g_wq);
    cudaGetSymbolAddress((void**)&wkp, g_wk);
    cudaGetSymbolAddress((void**)&wvp, g_wv);
    cudaGetSymbolAddress((void**)&wop, g_wo);
    cudaGetSymbolAddress((void**)&atp, g_att);

    cudaFuncSetAttribute(gemm_qkv_kernel, cudaFuncAttributeMaxDynamicSharedMemorySize, GEMM2_SMEM);
    cudaFuncSetAttribute(gemm_o_kernel,   cudaFuncAttributeMaxDynamicSharedMemorySize, GEMM2_SMEM);
    cudaFuncSetAttribute(rel_tc_kernel,   cudaFuncAttributeMaxDynamicSharedMemorySize, REL_SMEM);
    cudaFuncSetAttribute(attn_tc_kernel,  cudaFuncAttributeMaxDynamicSharedMemorySize, ATTN_SMEM);

    const int NG = NG_HS + 4 * NG_W;
    cvt5_kernel<<<(NG + 255) / 256, 256>>>(hs, w_q, w_k, w_v, w_o);
    gemm_qkv_kernel<<<dim3(18, SEQ/128), 256, GEMM2_SMEM>>>(hsp, wqp, wkp, wvp, b_q, b_k, b_v);
    rel_tc_kernel<<<dim3(64, NHEAD), 128, REL_SMEM>>>(rph, rpw);
    attn_tc_kernel<<<dim3(SEQ/128, NHEAD), 256, ATTN_SMEM>>>();
    gemm_o_kernel<<<dim3(CDIM/128, SEQ/128), 256, GEMM2_SMEM>>>(atp, wop, b_o, out);
}